// round 14
// baseline (speedup 1.0000x reference)
#include <cuda_runtime.h>

typedef unsigned long long ull;

#define NB_B   4096
#define NB_S   128
#define NB_D   9
#define NB_V   5
#define NB_BLK 4
#define RP     12

// log2(e)/3 : folds softmax scale (1/sqrt(9)) and exp->exp2 into the score form
#define QSCL   0.48089834696298784f

// ---- composed-parameter globals (written by prep_kernel, read by main) ----
__device__ float g_A[NB_BLK][NB_D][RP];   // A''_i rows: y = A'' u
__device__ float g_c[NB_BLK][RP];         // c''_i:     s0 = c''.u
__device__ float g_Wh[NB_V][RP];          // composed head weights
__device__ float g_bh[NB_V];              // composed head bias

// hardcoded inv_freq(d) = 10000^(-(2*(d//2))/9)
__device__ __constant__ const float c_invf[NB_D] = {
    1.0f, 1.0f,
    1.2915497e-1f, 1.2915497e-1f,
    1.6681005e-2f, 1.6681005e-2f,
    2.1544347e-3f, 2.1544347e-3f,
    2.7825594e-4f
};

// ---------- packed f32x2 helpers (Blackwell sm_103a) ----------
__device__ __forceinline__ ull pack2(float a, float b) {
    ull r; asm("mov.b64 %0, {%1,%2};" : "=l"(r) : "f"(a), "f"(b)); return r;
}
__device__ __forceinline__ void unpack2(ull v, float& a, float& b) {
    asm("mov.b64 {%0,%1}, %2;" : "=f"(a), "=f"(b) : "l"(v));
}
__device__ __forceinline__ ull fma2(ull a, ull b, ull c) {
    ull d; asm("fma.rn.f32x2 %0, %1, %2, %3;" : "=l"(d) : "l"(a), "l"(b), "l"(c)); return d;
}
__device__ __forceinline__ ull mul2(ull a, ull b) {
    ull d; asm("mul.rn.f32x2 %0, %1, %2;" : "=l"(d) : "l"(a), "l"(b)); return d;
}
__device__ __forceinline__ ull add2(ull a, ull b) {
    ull d; asm("add.rn.f32x2 %0, %1, %2;" : "=l"(d) : "l"(a), "l"(b)); return d;
}
__device__ __forceinline__ float ex2f(float x) {
    float y; asm("ex2.approx.f32 %0, %1;" : "=f"(y) : "f"(x)); return y;
}

// scalar row (9 floats, 16B-aligned) vs packed-x pair, NO bias (mul2 start)
__device__ __forceinline__ ull proj0(const float* __restrict__ wrow, const ull x[NB_D]) {
    float4 a = *(const float4*)(wrow);
    float4 b = *(const float4*)(wrow + 4);
    float  c = wrow[8];
    ull t = mul2(pack2(a.x,a.x), x[0]);
    t = fma2(pack2(a.y,a.y), x[1], t);
    t = fma2(pack2(a.z,a.z), x[2], t);
    t = fma2(pack2(a.w,a.w), x[3], t);
    t = fma2(pack2(b.x,b.x), x[4], t);
    t = fma2(pack2(b.y,b.y), x[5], t);
    t = fma2(pack2(b.z,b.z), x[6], t);
    t = fma2(pack2(b.w,b.w), x[7], t);
    t = fma2(pack2(c,c),     x[8], t);
    return t;
}

// with bias (head)
__device__ __forceinline__ ull proj1(const float* __restrict__ wrow, float bias,
                                     const ull x[NB_D]) {
    float4 a = *(const float4*)(wrow);
    float4 b = *(const float4*)(wrow + 4);
    float  c = wrow[8];
    ull t = pack2(bias, bias);
    t = fma2(pack2(a.x,a.x), x[0], t);
    t = fma2(pack2(a.y,a.y), x[1], t);
    t = fma2(pack2(a.z,a.z), x[2], t);
    t = fma2(pack2(a.w,a.w), x[3], t);
    t = fma2(pack2(b.x,b.x), x[4], t);
    t = fma2(pack2(b.y,b.y), x[5], t);
    t = fma2(pack2(b.z,b.z), x[6], t);
    t = fma2(pack2(b.w,b.w), x[7], t);
    t = fma2(pack2(c,c),     x[8], t);
    return t;
}

// =====================================================================
// prep kernel: compose per-block score forms and the affine state maps.
//   state: x_i = T u + t   (u = attention averages; u_0 = emb+PE)
//   scores_ij ~ u_i^T A'' u_j + c''.u_j   (per-i terms cancel in softmax)
//   A = QSCL*Wq^T Wk ; c = QSCL*Wk^T bq
//   A'' = T^T A T ; c'' = T^T (A^T t + c)
//   update: T <- Wv T ; t <- Wv t + bv
//   head:  Wh = Wout T4 ; bh = Wout t4 + bout
// =====================================================================
__global__ void prep_kernel(const float* __restrict__ Wq, const float* __restrict__ bq,
                            const float* __restrict__ Wk,
                            const float* __restrict__ Wv, const float* __restrict__ bv,
                            const float* __restrict__ Wout, const float* __restrict__ bout)
{
    __shared__ float T[81], Tn[81], A[81], AT[81];
    __shared__ float tv[9], tn[9], cv[9], vv[9];
    const int tid = threadIdx.x;
    const int a = tid / 9, bc = tid % 9;

    if (tid < 81) T[tid] = (a == bc) ? 1.f : 0.f;
    if (tid < 9)  tv[tid] = 0.f;
    __syncthreads();

    for (int i = 0; i < NB_BLK; ++i) {
        const float* wq = Wq + i * 81;
        const float* wk = Wk + i * 81;
        const float* wv = Wv + i * 81;
        if (tid < 81) {                       // A = QSCL * Wq^T Wk
            float s = 0.f;
            for (int e = 0; e < 9; ++e) s += wq[e*9 + a] * wk[e*9 + bc];
            A[tid] = s * QSCL;
        }
        if (tid < 9) {                        // c = QSCL * Wk^T bq
            float s = 0.f;
            for (int e = 0; e < 9; ++e) s += bq[i*9 + e] * wk[e*9 + tid];
            cv[tid] = s * QSCL;
        }
        __syncthreads();
        if (tid < 81) {                       // AT = A*T
            float s = 0.f;
            for (int k = 0; k < 9; ++k) s += A[a*9 + k] * T[k*9 + bc];
            AT[tid] = s;
        }
        if (tid < 9) {                        // vv = A^T t + c
            float s = cv[tid];
            for (int k = 0; k < 9; ++k) s += A[k*9 + tid] * tv[k];
            vv[tid] = s;
        }
        __syncthreads();
        if (tid < 81) {                       // A'' = T^T * AT
            float s = 0.f;
            for (int k = 0; k < 9; ++k) s += T[k*9 + a] * AT[k*9 + bc];
            g_A[i][a][bc] = s;
        }
        if (tid < 9) {                        // c'' = T^T vv
            float s = 0.f;
            for (int k = 0; k < 9; ++k) s += T[k*9 + tid] * vv[k];
            g_c[i][tid] = s;
        }
        if (tid < 81) {                       // Tn = Wv * T
            float s = 0.f;
            for (int k = 0; k < 9; ++k) s += wv[a*9 + k] * T[k*9 + bc];
            Tn[tid] = s;
        }
        if (tid < 9) {                        // tn = Wv t + bv
            float s = bv[i*9 + tid];
            for (int k = 0; k < 9; ++k) s += wv[tid*9 + k] * tv[k];
            tn[tid] = s;
        }
        __syncthreads();
        if (tid < 81) T[tid] = Tn[tid];
        if (tid < 9)  tv[tid] = tn[tid];
        __syncthreads();
    }

    if (tid < NB_V * 9) {                     // Wh = Wout * T4
        int v = tid / 9, bb = tid % 9;
        float s = 0.f;
        for (int k = 0; k < 9; ++k) s += Wout[v*9 + k] * T[k*9 + bb];
        g_Wh[v][bb] = s;
    }
    if (tid < NB_V) {                         // bh = Wout t4 + bout
        float s = bout[tid];
        for (int k = 0; k < 9; ++k) s += Wout[tid*9 + k] * tv[k];
        g_bh[tid] = s;
    }
}

// =====================================================================
// main kernel
// =====================================================================
__global__ __launch_bounds__(64, 12)
void bert_kernel(const int*   __restrict__ tokens,
                 const float* __restrict__ emb,
                 float* __restrict__ out)
{
    // ONE batch per 64-thread CTA (2 warps)
    __shared__ __align__(16) float sYt[NB_D][NB_S];          // transformed keys y
    __shared__ __align__(16) float sUt[NB_D][NB_S];          // state u
    __shared__ __align__(16) float s0t[NB_S];                // per-key score seed
    __shared__ __align__(16) float sA[NB_BLK][NB_D][RP];     // A'' rows
    __shared__ __align__(16) float sC[NB_BLK][RP];           // c''
    __shared__ __align__(16) float sWh[NB_V][RP];
    __shared__ __align__(16) float sEmb[NB_V][RP];
    __shared__ float sbh[NB_V];

    const int tid  = threadIdx.x;
    const int wh   = tid >> 5;
    const int lane = tid & 31;
    const int b    = blockIdx.x;

    // ---- load composed params ----
    for (int idx = tid; idx < NB_BLK * NB_D * NB_D; idx += 64) {
        int i = idx / 81, r = idx % 81;
        sA[i][r / 9][r % 9] = g_A[i][r / 9][r % 9];
    }
    if (tid < NB_BLK * NB_D) sC[tid / NB_D][tid % NB_D] = g_c[tid / NB_D][tid % NB_D];
    if (tid < NB_V * NB_D) {
        int v = tid / NB_D, d = tid % NB_D;
        sWh[v][d]  = g_Wh[v][d];
        sEmb[v][d] = emb[tid];
    }
    if (tid < NB_V) sbh[tid] = g_bh[tid];
    __syncthreads();

    // ---- u0 = emb[token] + PE for this lane's 2 positions ----
    const int posA = wh * 64 + lane;
    const int posB = posA + 32;
    ull x2[NB_D];
    {
        int tokA = tokens[b * NB_S + posA];
        int tokB = tokens[b * NB_S + posB];
        #pragma unroll
        for (int d = 0; d < NB_D; ++d) {
            float angA = (float)posA * c_invf[d];
            float angB = (float)posB * c_invf[d];
            float peA  = ((d & 1) == 0) ? __sinf(angA) : __cosf(angA);
            float peB  = ((d & 1) == 0) ? __sinf(angB) : __cosf(angB);
            x2[d] = pack2(sEmb[tokA][d] + peA, sEmb[tokB][d] + peB);
        }
    }

    #pragma unroll 1
    for (int blk = 0; blk < NB_BLK; ++blk) {
        // ---- key transform y = A'' u, seed s0 = c''.u ; store transposed ----
        #pragma unroll
        for (int e = 0; e < NB_D; ++e) {
            ull yy = proj0(&sA[blk][e][0], x2);
            float a, bb;
            unpack2(yy, a, bb);
            sYt[e][posA] = a;  sYt[e][posB] = bb;
            unpack2(x2[e], a, bb);
            sUt[e][posA] = a;  sUt[e][posB] = bb;
        }
        {
            ull s02 = proj0(&sC[blk][0], x2);
            float a, bb;
            unpack2(s02, a, bb);
            s0t[posA] = a;  s0t[posB] = bb;
        }
        __syncthreads();

        // duplicated queries (u) in registers
        ull qa[NB_D], qb[NB_D];
        #pragma unroll
        for (int d = 0; d < NB_D; ++d) {
            float a, bb; unpack2(x2[d], a, bb);
            qa[d] = pack2(a, a);
            qb[d] = pack2(bb, bb);
        }

        // ---- single-pass attention; accumulator packed over (qa,qb) ----
        ull acc[NB_D];
        #pragma unroll
        for (int d = 0; d < NB_D; ++d) acc[d] = 0ULL;
        ull den2 = 0ULL;

        #pragma unroll 4
        for (int g = 0; g < NB_S / 4; ++g) {
            // seeds (s0_k, s0_{k+1}) for key pairs; same for both queries
            const ulonglong2 sd = *(const ulonglong2*)&s0t[g*4];
            ull s00 = sd.x, s01 = sd.y, s10 = sd.x, s11 = sd.y;
            #pragma unroll
            for (int d = 0; d < NB_D; ++d) {
                const ulonglong2 kk = *(const ulonglong2*)&sYt[d][g*4];
                s00 = fma2(kk.x, qa[d], s00); s01 = fma2(kk.y, qa[d], s01);
                s10 = fma2(kk.x, qb[d], s10); s11 = fma2(kk.y, qb[d], s11);
            }
            float sa0, sa1, sa2, sa3, sb0, sb1, sb2, sb3;
            unpack2(s00, sa0, sa1);
            unpack2(s01, sa2, sa3);
            unpack2(s10, sb0, sb1);
            unpack2(s11, sb2, sb3);
            ull ep0 = pack2(ex2f(sa0), ex2f(sb0));
            ull ep1 = pack2(ex2f(sa1), ex2f(sb1));
            ull ep2 = pack2(ex2f(sa2), ex2f(sb2));
            ull ep3 = pack2(ex2f(sa3), ex2f(sb3));
            den2 = add2(den2, add2(add2(ep0, ep1), add2(ep2, ep3)));
            #pragma unroll
            for (int d = 0; d < NB_D; ++d) {
                const float4 v = *(const float4*)&sUt[d][g*4];
                acc[d] = fma2(ep0, pack2(v.x, v.x), acc[d]);
                acc[d] = fma2(ep1, pack2(v.y, v.y), acc[d]);
                acc[d] = fma2(ep2, pack2(v.z, v.z), acc[d]);
                acc[d] = fma2(ep3, pack2(v.w, v.w), acc[d]);
            }
        }

        float da, db;
        unpack2(den2, da, db);
        ull inv2 = pack2(__fdividef(1.f, da), __fdividef(1.f, db));
        #pragma unroll
        for (int d = 0; d < NB_D; ++d)
            x2[d] = mul2(acc[d], inv2);      // new u (no transform needed)

        __syncthreads();
    }

    // ---- composed output head: logits + log_softmax over V=5 ----
    ull lg2[NB_V];
    #pragma unroll
    for (int v = 0; v < NB_V; ++v)
        lg2[v] = proj1(&sWh[v][0], sbh[v], x2);

    #pragma unroll
    for (int half = 0; half < 2; ++half) {
        int pos = half == 0 ? posA : posB;
        float lg[NB_V];
        #pragma unroll
        for (int v = 0; v < NB_V; ++v) {
            float a, bb; unpack2(lg2[v], a, bb);
            lg[v] = half == 0 ? a : bb;
        }
        float mx = lg[0];
        #pragma unroll
        for (int v = 1; v < NB_V; ++v) mx = fmaxf(mx, lg[v]);
        float sum = 0.f;
        #pragma unroll
        for (int v = 0; v < NB_V; ++v) sum += __expf(lg[v] - mx);
        float lse = mx + __logf(sum);
        float* o = out + ((size_t)b * NB_S + pos) * NB_V;
        #pragma unroll
        for (int v = 0; v < NB_V; ++v) o[v] = lg[v] - lse;
    }
}

extern "C" void kernel_launch(void* const* d_in, const int* in_sizes, int n_in,
                              void* d_out, int out_size)
{
    const int*   tokens = (const int*)  d_in[0];
    const float* emb    = (const float*)d_in[1];
    const float* Wq     = (const float*)d_in[2];
    const float* bq     = (const float*)d_in[3];
    const float* Wk     = (const float*)d_in[4];
    // bk (d_in[5]) cancels in softmax — unused
    const float* Wv     = (const float*)d_in[6];
    const float* bv     = (const float*)d_in[7];
    const float* Wout   = (const float*)d_in[8];
    const float* bout   = (const float*)d_in[9];
    float* outp = (float*)d_out;

    prep_kernel<<<1, 96>>>(Wq, bq, Wk, Wv, bv, Wout, bout);
    bert_kernel<<<NB_B, 64>>>(tokens, emb, outp);
}